// round 12
// baseline (speedup 1.0000x reference)
#include <cuda_runtime.h>
#include <cuda_bf16.h>
#include <cstdint>

// Problem constants
#define NTOK   65536      // 16 * 64 * 64 tokens
#define DIM    256        // channels / code dim
#define NCODE  1024       // codebook entries
#define HW     4096       // 64*64
#define IMG_ELEMS 16777216 // 16*256*64*64

#define CAP    16         // candidate list capacity per token
#define DELTA  16.0f      // rescore margin on approx (int8) distances
#define QS     25.4f      // 127/5 quantization scale
// score = e2[k] - 2*(5/127)^2 * acc ; (5/127)^2 = 25/16129
#define DEQN2  (-50.0f / 16129.0f)

#define NGATHER (IMG_ELEMS / (256 * 4))   // gather grid size

// ---------------------------------------------------------------------------
// Device scratch
// ---------------------------------------------------------------------------
__device__ float  g_e2[NCODE];
__device__ int    g_ind[NTOK];
__device__ double g_loss;
__device__ unsigned g_done;
__device__ __align__(16) signed char g_ebq[(size_t)NCODE * DIM];  // e [code][d] s8
__device__ __align__(16) float       g_ebtf[(size_t)NCODE * DIM]; // e [code][d] fp32
__device__ int    g_cand[NTOK][CAP];
__device__ unsigned char g_ncand[NTOK];   // 255 = clipped token -> full exact scan

// ---------------------------------------------------------------------------
// PTX helpers (sm_80+ features only: valid at generic sm_103 target)
// ---------------------------------------------------------------------------
__device__ __forceinline__ uint32_t smem_to_u32(const void* p) {
    uint32_t a;
    asm("{ .reg .u64 t; cvta.to.shared.u64 t, %1; cvt.u32.u64 %0, t; }" : "=r"(a) : "l"(p));
    return a;
}
__device__ __forceinline__ void ldsm_x4(uint32_t& r0, uint32_t& r1, uint32_t& r2,
                                        uint32_t& r3, uint32_t addr) {
    asm volatile("ldmatrix.sync.aligned.m8n8.x4.shared.b16 {%0,%1,%2,%3}, [%4];"
                 : "=r"(r0), "=r"(r1), "=r"(r2), "=r"(r3) : "r"(addr));
}
__device__ __forceinline__ void mma_s8(int c[4], const uint32_t a[4], const uint32_t b[2]) {
    asm volatile("mma.sync.aligned.m16n8k32.row.col.s32.s8.s8.s32 "
                 "{%0,%1,%2,%3}, {%4,%5,%6,%7}, {%8,%9}, {%0,%1,%2,%3};"
                 : "+r"(c[0]), "+r"(c[1]), "+r"(c[2]), "+r"(c[3])
                 : "r"(a[0]), "r"(a[1]), "r"(a[2]), "r"(a[3]), "r"(b[0]), "r"(b[1]));
}
__device__ __forceinline__ void cp16(uint32_t dst, const void* src) {
    asm volatile("cp.async.cg.shared.global [%0], [%1], 16;" :: "r"(dst), "l"(src));
}
#define CP_COMMIT() asm volatile("cp.async.commit_group;" ::: "memory")
#define CP_WAIT(n)  asm volatile("cp.async.wait_group %0;" :: "n"(n) : "memory")

__device__ __forceinline__ int q8(float v) {
    return __float2int_rn(fminf(fmaxf(v * QS, -127.f), 127.f));
}

// monotone unsigned key for float ordering (handles negatives)
__device__ __forceinline__ unsigned long long packsc(float f, int col) {
    unsigned u = __float_as_uint(f);
    u ^= ((unsigned)((int)u >> 31)) | 0x80000000u;
    return ((unsigned long long)u << 32) | (unsigned)col;
}
__device__ __forceinline__ float unkeyf(unsigned u) {
    return (u & 0x80000000u) ? __uint_as_float(u ^ 0x80000000u)
                             : __uint_as_float(~u);
}

// ---------------------------------------------------------------------------
// Kernel A: per-code squared norms + zero loss/done
// ---------------------------------------------------------------------------
__global__ void e2_kernel(const float* __restrict__ embed) {
    int k = blockIdx.x * 256 + threadIdx.x;
    float s = 0.f;
    #pragma unroll 8
    for (int d = 0; d < DIM; ++d) {
        float v = embed[d * NCODE + k];
        s = fmaf(v, v, s);
    }
    g_e2[k] = s;
    if (k == 0) { g_loss = 0.0; g_done = 0u; }
}

// ---------------------------------------------------------------------------
// Kernel P: transpose embed [d][k] -> code-major fp32 + s8 quantized copies
// ---------------------------------------------------------------------------
__global__ void __launch_bounds__(256)
prep_e_kernel(const float* __restrict__ embed) {
    __shared__ float t[32][33];
    int d0 = blockIdx.y << 5;
    int k0 = blockIdx.x << 5;
    const float* src = embed + (size_t)d0 * NCODE + k0;
    #pragma unroll
    for (int i = 0; i < 32; i += 8)
        t[threadIdx.y + i][threadIdx.x] = src[(size_t)(threadIdx.y + i) * NCODE + threadIdx.x];
    __syncthreads();
    size_t obase = (size_t)k0 * DIM + d0;
    #pragma unroll
    for (int i = 0; i < 32; i += 8) {
        float v = t[threadIdx.x][threadIdx.y + i];
        size_t o = obase + (size_t)(threadIdx.y + i) * DIM + threadIdx.x;
        g_ebtf[o] = v;
        g_ebq[o]  = (signed char)q8(v);
    }
}

// ---------------------------------------------------------------------------
// Stage 1: int8 mma.sync (m16n8k32) scoring. 16 warps (512 thr), warp grid
// 4M x 4N, warp tile 32x32. M=128 tokens, N=128 codes/iter, K=256 (8 k-steps
// of 32), 8 N-iters. A quantized in-kernel from NCHW x (with clip flags);
// B double-buffered via cp.async. Rows 272B (17x16B) => conflict-free ldsm.
// ---------------------------------------------------------------------------
#define LDA      272
#define S_A      0
#define S_B      34816          // 128*272
#define S_BSZ    34816
#define S_E2     104448         // S_B + 2*S_BSZ (4KB)
#define S_G1     108544         // 128 x ull
#define S_CNT    109568         // 128 x int
#define S_CLIP   110080         // 128 x int
#define S_TOTAL  110592

__global__ void __launch_bounds__(512, 1)
vq_mma_kernel(const float* __restrict__ x) {
    extern __shared__ char smem[];
    const uint32_t sb  = smem_to_u32(smem);
    const int tid   = threadIdx.x;
    const int lane  = tid & 31;
    const int wid   = tid >> 5;
    const int warpM = wid >> 2;       // 0..3 -> rows warpM*32..+32
    const int warpN = wid & 3;        // 0..3 -> cols warpN*32..+32 per iter
    const int tok0  = blockIdx.x << 7;

    float* e2s = (float*)(smem + S_E2);
    unsigned long long* sG1 = (unsigned long long*)(smem + S_G1);
    int* scnt  = (int*)(smem + S_CNT);
    int* sclip = (int*)(smem + S_CLIP);

    if (tid < 128) { sG1[tid] = 0xFFFFFFFFFFFFFFFFull; sclip[tid] = 0; }
    __syncthreads();   // init visible before clip-flag writes below

    // async-load B subtile 'sub' (128 codes x 256 s8) into buffer
    auto load_B = [&](int buf, int sub) {
        const char* src = (const char*)(g_ebq + ((size_t)sub << 7) * DIM);
        uint32_t dst = sb + S_B + buf * S_BSZ;
        #pragma unroll
        for (int j = 0; j < 4; ++j) {
            int idx = tid + (j << 9);     // 0..2047 16B chunks
            int r = idx >> 4, c = idx & 15;
            cp16(dst + r * LDA + c * 16, src + r * 256 + c * 16);
        }
    };
    load_B(0, 0);
    CP_COMMIT();                        // group0 = B0

    // A tile: quantize x (NCHW, fp32) -> smem [token(hw)][d] s8, fused transpose.
    {
        const int bimg = tok0 >> 12;
        const int hwb  = tok0 & 4095;
        const float* xb = x + (size_t)bimg * DIM * HW + hwb;
        #pragma unroll
        for (int j = 0; j < 4; ++j) {
            int bb = tid + (j << 9);
            int x1 = bb & 7, x2 = (bb >> 3) & 3, x3 = (bb >> 5) & 15, x4 = bb >> 9;
            int h0 = 4 * x1 + 32 * x4;
            int d0 = 4 * x2 + 16 * x3;
            float4 v[4];
            #pragma unroll
            for (int i = 0; i < 4; ++i)
                v[i] = *(const float4*)(xb + (size_t)(d0 + i) * HW + h0);
            #pragma unroll
            for (int r = 0; r < 4; ++r) {
                float f0 = (r == 0) ? v[0].x : (r == 1) ? v[0].y : (r == 2) ? v[0].z : v[0].w;
                float f1 = (r == 0) ? v[1].x : (r == 1) ? v[1].y : (r == 2) ? v[1].z : v[1].w;
                float f2 = (r == 0) ? v[2].x : (r == 1) ? v[2].y : (r == 2) ? v[2].z : v[2].w;
                float f3 = (r == 0) ? v[3].x : (r == 1) ? v[3].y : (r == 2) ? v[3].z : v[3].w;
                float am = fmaxf(fmaxf(fabsf(f0), fabsf(f1)), fmaxf(fabsf(f2), fabsf(f3)));
                if (am * QS > 127.49f) sclip[h0 + r] = 1;   // benign race, same value
                uint32_t pk = (uint32_t)(q8(f0) & 0xff)
                            | ((uint32_t)(q8(f1) & 0xff) << 8)
                            | ((uint32_t)(q8(f2) & 0xff) << 16)
                            | ((uint32_t)(q8(f3) & 0xff) << 24);
                *(uint32_t*)(smem + S_A + (h0 + r) * LDA + d0) = pk;
            }
        }
    }

    #pragma unroll
    for (int j = 0; j < 2; ++j) e2s[tid + (j << 9)] = g_e2[tid + (j << 9)];

    // per-thread top-4 per row-slot (4 slots: 2 mtiles x 2 row-halves)
    float bv[4][4];
    int   kv[4][4];
    #pragma unroll
    for (int s = 0; s < 4; ++s)
        #pragma unroll
        for (int r = 0; r < 4; ++r) { bv[s][r] = 3.4e38f; kv[s][r] = 0; }

    // ldmatrix lane addressing (s8 k32: same byte pattern as validated bf16 k16)
    uint32_t aA[2];
    #pragma unroll
    for (int mt = 0; mt < 2; ++mt)
        aA[mt] = sb + S_A
               + (uint32_t)((warpM * 32 + mt * 16 + (lane & 15)) * LDA)
               + (uint32_t)((lane >> 4) * 16);
    const uint32_t bRowOff =
        (uint32_t)((warpN * 32 + ((lane >> 4) & 1) * 8 + (lane & 7)) * LDA)
        + (uint32_t)(((lane >> 3) & 1) * 16);

    #pragma unroll 1
    for (int it = 0; it < 8; ++it) {
        int buf = it & 1;
        if (it + 1 < 8) { load_B(buf ^ 1, it + 1); CP_COMMIT(); CP_WAIT(1); }
        else            { CP_WAIT(0); }
        __syncthreads();

        int c[2][4][4];
        #pragma unroll
        for (int mt = 0; mt < 2; ++mt)
            #pragma unroll
            for (int nt = 0; nt < 4; ++nt)
                #pragma unroll
                for (int e = 0; e < 4; ++e) c[mt][nt][e] = 0;

        const uint32_t bBase = sb + S_B + buf * S_BSZ + bRowOff;

        #pragma unroll
        for (int k = 0; k < 8; ++k) {       // 8 k-steps x 32 dims
            uint32_t a[2][4];
            #pragma unroll
            for (int mt = 0; mt < 2; ++mt)
                ldsm_x4(a[mt][0], a[mt][1], a[mt][2], a[mt][3],
                        aA[mt] + (uint32_t)(k * 32));
            uint32_t b[4][2];
            #pragma unroll
            for (int p = 0; p < 2; ++p) {
                uint32_t r0, r1, r2, r3;
                ldsm_x4(r0, r1, r2, r3,
                        bBase + (uint32_t)(p * 16 * LDA) + (uint32_t)(k * 32));
                b[2 * p][0] = r0; b[2 * p][1] = r1;
                b[2 * p + 1][0] = r2; b[2 * p + 1][1] = r3;
            }
            #pragma unroll
            for (int mt = 0; mt < 2; ++mt)
                #pragma unroll
                for (int nt = 0; nt < 4; ++nt)
                    mma_s8(c[mt][nt], a[mt], b[nt]);
        }

        // epilogue: scores -> per-thread top-4 per row slot
        #pragma unroll
        for (int mt = 0; mt < 2; ++mt)
            #pragma unroll
            for (int nt = 0; nt < 4; ++nt)
                #pragma unroll
                for (int e = 0; e < 4; ++e) {
                    const int s   = mt * 2 + (e >> 1);
                    const int col = (it << 7) + warpN * 32 + nt * 8
                                  + 2 * (lane & 3) + (e & 1);
                    float sc = fmaf((float)c[mt][nt][e], DEQN2, e2s[col]);
                    if (sc < bv[s][3]) {
                        if (sc < bv[s][2]) {
                            bv[s][3] = bv[s][2]; kv[s][3] = kv[s][2];
                            if (sc < bv[s][1]) {
                                bv[s][2] = bv[s][1]; kv[s][2] = kv[s][1];
                                if (sc < bv[s][0]) {
                                    bv[s][1] = bv[s][0]; kv[s][1] = kv[s][0];
                                    bv[s][0] = sc; kv[s][0] = col;
                                } else { bv[s][1] = sc; kv[s][1] = col; }
                            } else { bv[s][2] = sc; kv[s][2] = col; }
                        } else { bv[s][3] = sc; kv[s][3] = col; }
                    }
                }
        __syncthreads();   // all warps done reading buf before overwrite
    }

    // ---- Block-exact merge across the 16 owners of each token row ----
    #pragma unroll
    for (int s = 0; s < 4; ++s) {
        const int lt = warpM * 32 + (s >> 1) * 16 + (s & 1) * 8 + (lane >> 2);
        atomicMin(&sG1[lt], packsc(bv[s][0], kv[s][0]));
    }
    __syncthreads();
    if (tid < 128) {
        g_cand[tok0 + tid][0] = (int)(sG1[tid] & 0xFFFFFFFFull);
        scnt[tid] = 1;
    }
    __syncthreads();
    #pragma unroll
    for (int s = 0; s < 4; ++s) {
        const int lt  = warpM * 32 + (s >> 1) * 16 + (s & 1) * 8 + (lane >> 2);
        const int tok = tok0 + lt;
        unsigned long long g = sG1[lt];
        int   gk = (int)(g & 0xFFFFFFFFull);
        float gv = unkeyf((unsigned)(g >> 32));
        #pragma unroll
        for (int r = 0; r < 4; ++r) {
            bool dup = (r == 0) && (kv[s][0] == gk);
            if (!dup && bv[s][r] < gv + DELTA) {
                int p = atomicAdd(&scnt[lt], 1);
                if (p < CAP) g_cand[tok][p] = kv[s][r];
            }
        }
    }
    __syncthreads();
    if (tid < 128) {
        int n = scnt[tid] < CAP ? scnt[tid] : CAP;
        g_ncand[tok0 + tid] = (unsigned char)(sclip[tid] ? 255 : n);
    }
}

// ---------------------------------------------------------------------------
// Stage 2: exact fp32 rescore, block = 32 consecutive tokens (256 thr).
// x staged COALESCED from NCHW into smem (tokens are hw-contiguous), then
// warp w rescores tokens 4w..4w+3 with the R5/R8-validated lane-parallel
// dot + shfl reduction. n==255 (clipped) -> full 1024-code scan.
// ---------------------------------------------------------------------------
__global__ void __launch_bounds__(256)
rescore_kernel(const float* __restrict__ x) {
    __shared__ float xs[32][257];     // [token-local][d], pad 257 -> conflict-free
    const int wid = threadIdx.x >> 5;
    const int lid = threadIdx.x & 31;
    const int tok0 = blockIdx.x << 5;         // 32 tokens, same image (32 | 4096)
    const int bimg = tok0 >> 12;
    const int hw0  = tok0 & 4095;

    // coalesced staging: warp w loads channel d = wid + 8j for 32 tokens
    {
        const float* xb = x + (size_t)bimg * DIM * HW + hw0;
        #pragma unroll 8
        for (int j = 0; j < 32; ++j) {
            int d = wid + (j << 3);
            xs[lid][d] = xb[(size_t)d * HW + lid];
        }
    }
    __syncthreads();

    #pragma unroll 1
    for (int tt = 0; tt < 4; ++tt) {
        const int lt  = (wid << 2) + tt;
        const int tok = tok0 + lt;
        int n = g_ncand[tok];
        if (n <= 1) {
            if (lid == 0) g_ind[tok] = g_cand[tok][0];
            continue;
        }

        float bs = 3.4e38f;
        int   bk = 0x7fffffff;
        const bool full = (n == 255);
        const int total = full ? NCODE : n;

        #pragma unroll 1
        for (int i = 0; i < total; ++i) {
            int k = full ? i : g_cand[tok][i];
            const float* er = g_ebtf + (size_t)k * DIM;
            float acc = 0.f;
            #pragma unroll
            for (int j = 0; j < 8; ++j)
                acc = fmaf(xs[lt][lid + (j << 5)], er[lid + (j << 5)], acc);
            #pragma unroll
            for (int off = 16; off > 0; off >>= 1)
                acc += __shfl_xor_sync(0xffffffffu, acc, off);
            float s = fmaf(-2.f, acc, g_e2[k]);
            if (s < bs || (s == bs && k < bk)) { bs = s; bk = k; }
        }
        if (lid == 0) g_ind[tok] = bk;
    }
}

// ---------------------------------------------------------------------------
// Kernel C: gather to NCHW output + MSE loss + fused finalize (last block).
// ---------------------------------------------------------------------------
__global__ void __launch_bounds__(256)
gather_kernel(const float* __restrict__ x, const float* __restrict__ embed,
              float* __restrict__ outImg, float* __restrict__ outLoss) {
    size_t g = (((size_t)blockIdx.x << 8) + threadIdx.x) << 2;
    int n   = (int)(g >> 20);
    int rem = (int)(g & 1048575);
    int d   = rem >> 12;
    int hw  = rem & 4095;
    int tok = (n << 12) + hw;

    const float* erow = embed + d * NCODE;
    float q0 = erow[g_ind[tok + 0]];
    float q1 = erow[g_ind[tok + 1]];
    float q2 = erow[g_ind[tok + 2]];
    float q3 = erow[g_ind[tok + 3]];

    float4 xv = *(const float4*)(x + g);

    // scalar stores: outImg = d_out + 1 is only 4-byte aligned
    outImg[g + 0] = q0;
    outImg[g + 1] = q1;
    outImg[g + 2] = q2;
    outImg[g + 3] = q3;

    float d0 = q0 - xv.x, d1 = q1 - xv.y, d2 = q2 - xv.z, d3 = q3 - xv.w;
    float local = d0 * d0 + d1 * d1 + d2 * d2 + d3 * d3;

    #pragma unroll
    for (int off = 16; off > 0; off >>= 1)
        local += __shfl_down_sync(0xffffffffu, local, off);
    __shared__ float warpsum[8];
    int wid = threadIdx.x >> 5, lid = threadIdx.x & 31;
    if (lid == 0) warpsum[wid] = local;
    __syncthreads();
    if (threadIdx.x == 0) {
        float s = 0.f;
        #pragma unroll
        for (int w = 0; w < 8; ++w) s += warpsum[w];
        atomicAdd(&g_loss, (double)s);
        __threadfence();
        unsigned t = atomicInc(&g_done, 0xffffffffu);
        if (t == NGATHER - 1 && outLoss) {
            double total = atomicAdd(&g_loss, 0.0);   // ordered read
            outLoss[0] = (float)(0.25 * total / (double)IMG_ELEMS);
        }
    }
}

// ---------------------------------------------------------------------------
extern "C" void kernel_launch(void* const* d_in, const int* in_sizes, int n_in,
                              void* d_out, int out_size) {
    const float* x     = (const float*)d_in[0];   // [16,256,64,64] fp32
    const float* embed = (const float*)d_in[1];   // [256,1024] fp32
    float* out = (float*)d_out;

    int off = out_size - IMG_ELEMS;               // expected 1 (loss scalar first)
    float* outImg  = out + (off > 0 ? off : 0);
    float* outLoss = (off > 0) ? out : nullptr;

    cudaFuncSetAttribute(vq_mma_kernel,
                         cudaFuncAttributeMaxDynamicSharedMemorySize, S_TOTAL);

    e2_kernel<<<NCODE / 256, 256>>>(embed);
    prep_e_kernel<<<dim3(NCODE / 32, DIM / 32, 1), dim3(32, 8)>>>(embed);
    vq_mma_kernel<<<NTOK / 128, 512, S_TOTAL>>>(x);
    rescore_kernel<<<NTOK / 32, 256>>>(x);
    gather_kernel<<<NGATHER, 256>>>(x, embed, outImg, outLoss);
}

// round 13
// speedup vs baseline: 3.6435x; 3.6435x over previous
#include <cuda_runtime.h>
#include <cuda_bf16.h>
#include <cstdint>

// Problem constants
#define NTOK   65536      // 16 * 64 * 64 tokens
#define DIM    256        // channels / code dim
#define NCODE  1024       // codebook entries
#define HW     4096       // 64*64
#define IMG_ELEMS 16777216 // 16*256*64*64

#define CAP    8          // candidate list capacity per token
#define DELTA  1.0f       // rescore margin on approx (bf16) distances — validated R5/R8

#define NGATHER (IMG_ELEMS / (256 * 4))   // gather grid size

// ---------------------------------------------------------------------------
// Device scratch
// ---------------------------------------------------------------------------
__device__ float  g_e2[NCODE];
__device__ int    g_ind[NTOK];
__device__ double g_loss;
__device__ unsigned g_done;
__device__ __align__(16) __nv_bfloat16 g_ebt[(size_t)NCODE * DIM]; // e [code][d] bf16
__device__ __align__(16) float         g_ebtf[(size_t)NCODE * DIM];// e [code][d] fp32
__device__ int    g_cand[NTOK][CAP];
__device__ unsigned char g_ncand[NTOK];

// ---------------------------------------------------------------------------
// PTX helpers (sm_80+ features only: valid at generic sm_103 target)
// ---------------------------------------------------------------------------
__device__ __forceinline__ uint32_t smem_to_u32(const void* p) {
    uint32_t a;
    asm("{ .reg .u64 t; cvta.to.shared.u64 t, %1; cvt.u32.u64 %0, t; }" : "=r"(a) : "l"(p));
    return a;
}
__device__ __forceinline__ void ldsm_x4(uint32_t& r0, uint32_t& r1, uint32_t& r2,
                                        uint32_t& r3, uint32_t addr) {
    asm volatile("ldmatrix.sync.aligned.m8n8.x4.shared.b16 {%0,%1,%2,%3}, [%4];"
                 : "=r"(r0), "=r"(r1), "=r"(r2), "=r"(r3) : "r"(addr));
}
__device__ __forceinline__ void mma_bf16(float c[4], const uint32_t a[4],
                                         const uint32_t b[2]) {
    asm volatile("mma.sync.aligned.m16n8k16.row.col.f32.bf16.bf16.f32 "
                 "{%0,%1,%2,%3}, {%4,%5,%6,%7}, {%8,%9}, {%0,%1,%2,%3};"
                 : "+f"(c[0]), "+f"(c[1]), "+f"(c[2]), "+f"(c[3])
                 : "r"(a[0]), "r"(a[1]), "r"(a[2]), "r"(a[3]), "r"(b[0]), "r"(b[1]));
}
__device__ __forceinline__ void cp16(uint32_t dst, const void* src) {
    asm volatile("cp.async.cg.shared.global [%0], [%1], 16;" :: "r"(dst), "l"(src));
}
#define CP_COMMIT() asm volatile("cp.async.commit_group;" ::: "memory")
#define CP_WAIT(n)  asm volatile("cp.async.wait_group %0;" :: "n"(n) : "memory")

__device__ __forceinline__ uint16_t bf16bits(float v) {
    __nv_bfloat16 b = __float2bfloat16(v);
    return __bfloat16_as_ushort(b);
}

// monotone unsigned key for float ordering (handles negatives)
__device__ __forceinline__ unsigned long long packsc(float f, int col) {
    unsigned u = __float_as_uint(f);
    u ^= ((unsigned)((int)u >> 31)) | 0x80000000u;
    return ((unsigned long long)u << 32) | (unsigned)col;
}
__device__ __forceinline__ float unkeyf(unsigned u) {
    return (u & 0x80000000u) ? __uint_as_float(u ^ 0x80000000u)
                             : __uint_as_float(~u);
}

// ---------------------------------------------------------------------------
// Kernel A: per-code squared norms + zero loss/done
// ---------------------------------------------------------------------------
__global__ void e2_kernel(const float* __restrict__ embed) {
    int k = blockIdx.x * 256 + threadIdx.x;
    float s = 0.f;
    #pragma unroll 8
    for (int d = 0; d < DIM; ++d) {
        float v = embed[d * NCODE + k];
        s = fmaf(v, v, s);
    }
    g_e2[k] = s;
    if (k == 0) { g_loss = 0.0; g_done = 0u; }
}

// ---------------------------------------------------------------------------
// Kernel P: transpose embed [d][k] -> code-major (bf16 + fp32 copies)
// ---------------------------------------------------------------------------
__global__ void __launch_bounds__(256)
prep_e_kernel(const float* __restrict__ embed) {
    __shared__ float t[32][33];
    int d0 = blockIdx.y << 5;
    int k0 = blockIdx.x << 5;
    const float* src = embed + (size_t)d0 * NCODE + k0;
    #pragma unroll
    for (int i = 0; i < 32; i += 8)
        t[threadIdx.y + i][threadIdx.x] = src[(size_t)(threadIdx.y + i) * NCODE + threadIdx.x];
    __syncthreads();
    size_t obase = (size_t)k0 * DIM + d0;
    #pragma unroll
    for (int i = 0; i < 32; i += 8) {
        float v = t[threadIdx.x][threadIdx.y + i];
        size_t o = obase + (size_t)(threadIdx.y + i) * DIM + threadIdx.x;
        g_ebtf[o] = v;
        g_ebt[o]  = __float2bfloat16(v);
    }
}

// ---------------------------------------------------------------------------
// Stage 1: bf16 mma.sync scoring (R8 core, validated): 16 warps (512 thr),
// warp grid 4M x 4N, warp tile 32x32. M=128 tokens, N=128 codes/iter, K=256,
// 8 iters. A produced IN-KERNEL (fused NCHW->bf16 transpose-quantize);
// B double-buffered via cp.async. 528B rows => conflict-free ldmatrix.
// ---------------------------------------------------------------------------
#define LDA      528
#define S_A      0
#define S_B      67584          // 128*528
#define S_BSZ    67584
#define S_E2     202752         // S_B + 2*S_BSZ (4KB)
#define S_G1     206848         // 128 x ull
#define S_CNT    207872         // 128 x int
#define S_TOTAL  208384

__global__ void __launch_bounds__(512, 1)
vq_mma_kernel(const float* __restrict__ x) {
    extern __shared__ char smem[];
    const uint32_t sb  = smem_to_u32(smem);
    const int tid   = threadIdx.x;
    const int lane  = tid & 31;
    const int wid   = tid >> 5;
    const int warpM = wid >> 2;       // 0..3 -> rows warpM*32..+32
    const int warpN = wid & 3;        // 0..3 -> cols warpN*32..+32 per iter
    const int tok0  = blockIdx.x << 7;

    float* e2s = (float*)(smem + S_E2);
    unsigned long long* sG1 = (unsigned long long*)(smem + S_G1);
    int* scnt = (int*)(smem + S_CNT);

    // async-load B subtile 'sub' (128 codes x 256 bf16) into buffer
    auto load_B = [&](int buf, int sub) {
        const char* src = (const char*)(g_ebt + ((size_t)sub << 7) * DIM);
        uint32_t dst = sb + S_B + buf * S_BSZ;
        #pragma unroll
        for (int j = 0; j < 8; ++j) {
            int idx = tid + (j << 9);     // 0..4095 16B chunks
            int r = idx >> 5, c = idx & 31;
            cp16(dst + r * LDA + c * 16, src + r * 512 + c * 16);
        }
    };
    load_B(0, 0);
    CP_COMMIT();                        // group0 = B0

    // A tile: fused transpose-quantize x (NCHW fp32) -> smem [token][d] bf16.
    // 4x4 blocks (validated R12 addressing): coalesced float4 LDGs, uint2 STS.
    {
        const int bimg = tok0 >> 12;
        const int hwb  = tok0 & 4095;
        const float* xb = x + (size_t)bimg * DIM * HW + hwb;
        #pragma unroll
        for (int j = 0; j < 4; ++j) {
            int bb = tid + (j << 9);
            int x1 = bb & 7, x2 = (bb >> 3) & 3, x3 = (bb >> 5) & 15, x4 = bb >> 9;
            int h0 = 4 * x1 + 32 * x4;     // token-local row
            int d0 = 4 * x2 + 16 * x3;     // channel
            float4 v[4];
            #pragma unroll
            for (int i = 0; i < 4; ++i)
                v[i] = *(const float4*)(xb + (size_t)(d0 + i) * HW + h0);
            #pragma unroll
            for (int r = 0; r < 4; ++r) {
                float f0 = (r == 0) ? v[0].x : (r == 1) ? v[0].y : (r == 2) ? v[0].z : v[0].w;
                float f1 = (r == 0) ? v[1].x : (r == 1) ? v[1].y : (r == 2) ? v[1].z : v[1].w;
                float f2 = (r == 0) ? v[2].x : (r == 1) ? v[2].y : (r == 2) ? v[2].z : v[2].w;
                float f3 = (r == 0) ? v[3].x : (r == 1) ? v[3].y : (r == 2) ? v[3].z : v[3].w;
                uint2 pk;
                pk.x = (uint32_t)bf16bits(f0) | ((uint32_t)bf16bits(f1) << 16);
                pk.y = (uint32_t)bf16bits(f2) | ((uint32_t)bf16bits(f3) << 16);
                *(uint2*)(smem + S_A + (h0 + r) * LDA + d0 * 2) = pk;
            }
        }
    }

    #pragma unroll
    for (int j = 0; j < 2; ++j) e2s[tid + (j << 9)] = g_e2[tid + (j << 9)];
    if (tid < 128) sG1[tid] = 0xFFFFFFFFFFFFFFFFull;

    // per-thread top-2 per row-slot (4 slots: 2 mtiles x 2 row-halves)
    float b1v[4], b2v[4];
    int   k1v[4], k2v[4];
    #pragma unroll
    for (int s = 0; s < 4; ++s) { b1v[s] = 3.4e38f; b2v[s] = 3.4e38f; k1v[s] = 0; k2v[s] = 0; }

    // ldmatrix lane addressing (identical fragment mapping to validated R5/R8)
    uint32_t aA[2];
    #pragma unroll
    for (int mt = 0; mt < 2; ++mt)
        aA[mt] = sb + S_A
               + (uint32_t)((warpM * 32 + mt * 16 + (lane & 15)) * LDA)
               + (uint32_t)((lane >> 4) * 16);
    const uint32_t bRowOff =
        (uint32_t)((warpN * 32 + ((lane >> 4) & 1) * 8 + (lane & 7)) * LDA)
        + (uint32_t)(((lane >> 3) & 1) * 16);

    #pragma unroll 1
    for (int it = 0; it < 8; ++it) {
        int buf = it & 1;
        if (it + 1 < 8) { load_B(buf ^ 1, it + 1); CP_COMMIT(); CP_WAIT(1); }
        else            { CP_WAIT(0); }
        __syncthreads();

        float c[2][4][4];
        #pragma unroll
        for (int mt = 0; mt < 2; ++mt)
            #pragma unroll
            for (int nt = 0; nt < 4; ++nt)
                #pragma unroll
                for (int e = 0; e < 4; ++e) c[mt][nt][e] = 0.f;

        const uint32_t bBase = sb + S_B + buf * S_BSZ + bRowOff;

        #pragma unroll 4
        for (int k = 0; k < 256; k += 16) {
            uint32_t a[2][4];
            #pragma unroll
            for (int mt = 0; mt < 2; ++mt)
                ldsm_x4(a[mt][0], a[mt][1], a[mt][2], a[mt][3],
                        aA[mt] + (uint32_t)(k * 2));
            uint32_t b[4][2];
            #pragma unroll
            for (int p = 0; p < 2; ++p) {
                uint32_t r0, r1, r2, r3;
                ldsm_x4(r0, r1, r2, r3,
                        bBase + (uint32_t)(p * 16 * LDA) + (uint32_t)(k * 2));
                b[2 * p][0] = r0; b[2 * p][1] = r1;
                b[2 * p + 1][0] = r2; b[2 * p + 1][1] = r3;
            }
            #pragma unroll
            for (int mt = 0; mt < 2; ++mt)
                #pragma unroll
                for (int nt = 0; nt < 4; ++nt)
                    mma_bf16(c[mt][nt], a[mt], b[nt]);
        }

        // epilogue: fold scores into per-thread top-2 per row slot
        #pragma unroll
        for (int mt = 0; mt < 2; ++mt)
            #pragma unroll
            for (int nt = 0; nt < 4; ++nt)
                #pragma unroll
                for (int e = 0; e < 4; ++e) {
                    const int s   = mt * 2 + (e >> 1);
                    const int col = (it << 7) + warpN * 32 + nt * 8
                                  + 2 * (lane & 3) + (e & 1);
                    float sc = fmaf(-2.f, c[mt][nt][e], e2s[col]);
                    if (sc < b2v[s]) {
                        if (sc < b1v[s]) {
                            b2v[s] = b1v[s]; k2v[s] = k1v[s];
                            b1v[s] = sc;     k1v[s] = col;
                        } else { b2v[s] = sc; k2v[s] = col; }
                    }
                }
        __syncthreads();   // all warps done reading buf before overwrite
    }

    // ---- Block-exact merge across the 16 owners of each token row ----
    #pragma unroll
    for (int s = 0; s < 4; ++s) {
        const int lt = warpM * 32 + (s >> 1) * 16 + (s & 1) * 8 + (lane >> 2);
        atomicMin(&sG1[lt], packsc(b1v[s], k1v[s]));
    }
    __syncthreads();
    if (tid < 128) {
        g_cand[tok0 + tid][0] = (int)(sG1[tid] & 0xFFFFFFFFull);
        scnt[tid] = 1;
    }
    __syncthreads();
    #pragma unroll
    for (int s = 0; s < 4; ++s) {
        const int lt  = warpM * 32 + (s >> 1) * 16 + (s & 1) * 8 + (lane >> 2);
        const int tok = tok0 + lt;
        unsigned long long g = sG1[lt];
        int   gk = (int)(g & 0xFFFFFFFFull);
        float gv = unkeyf((unsigned)(g >> 32));
        if (k1v[s] != gk && b1v[s] < gv + DELTA) {
            int p = atomicAdd(&scnt[lt], 1);
            if (p < CAP) g_cand[tok][p] = k1v[s];
        }
        if (b2v[s] < gv + DELTA) {
            int p = atomicAdd(&scnt[lt], 1);
            if (p < CAP) g_cand[tok][p] = k2v[s];
        }
    }
    __syncthreads();
    if (tid < 128)
        g_ncand[tok0 + tid] = (unsigned char)(scnt[tid] < CAP ? scnt[tid] : CAP);
}

// ---------------------------------------------------------------------------
// Stage 2: exact fp32 rescore, block = 32 consecutive tokens (256 thr).
// x staged COALESCED from NCHW into smem; warp w rescores tokens 4w..4w+3
// with the R5/R8-validated lane-parallel dot + shfl reduction.
// ---------------------------------------------------------------------------
__global__ void __launch_bounds__(256)
rescore_kernel(const float* __restrict__ x) {
    __shared__ float xs[32][257];     // [token-local][d], pad -> conflict-free
    const int wid = threadIdx.x >> 5;
    const int lid = threadIdx.x & 31;
    const int tok0 = blockIdx.x << 5;         // 32 tokens, same image (32 | 4096)
    const int bimg = tok0 >> 12;
    const int hw0  = tok0 & 4095;

    // coalesced staging: warp w loads channel d = wid + 8j for 32 tokens
    {
        const float* xb = x + (size_t)bimg * DIM * HW + hw0;
        #pragma unroll 8
        for (int j = 0; j < 32; ++j) {
            int d = wid + (j << 3);
            xs[lid][d] = xb[(size_t)d * HW + lid];
        }
    }
    __syncthreads();

    #pragma unroll 1
    for (int tt = 0; tt < 4; ++tt) {
        const int lt  = (wid << 2) + tt;
        const int tok = tok0 + lt;
        int n = g_ncand[tok];
        if (n <= 1) {
            if (lid == 0) g_ind[tok] = g_cand[tok][0];
            continue;
        }

        float bs = 3.4e38f;
        int   bk = 0x7fffffff;
        #pragma unroll 1
        for (int i = 0; i < n; ++i) {
            int k = g_cand[tok][i];
            const float* er = g_ebtf + (size_t)k * DIM;
            float acc = 0.f;
            #pragma unroll
            for (int j = 0; j < 8; ++j)
                acc = fmaf(xs[lt][lid + (j << 5)], er[lid + (j << 5)], acc);
            #pragma unroll
            for (int off = 16; off > 0; off >>= 1)
                acc += __shfl_xor_sync(0xffffffffu, acc, off);
            float s = fmaf(-2.f, acc, g_e2[k]);
            if (s < bs || (s == bs && k < bk)) { bs = s; bk = k; }
        }
        if (lid == 0) g_ind[tok] = bk;
    }
}

// ---------------------------------------------------------------------------
// Kernel C: gather to NCHW output + MSE loss + fused finalize (last block).
// ---------------------------------------------------------------------------
__global__ void __launch_bounds__(256)
gather_kernel(const float* __restrict__ x, const float* __restrict__ embed,
              float* __restrict__ outImg, float* __restrict__ outLoss) {
    size_t g = (((size_t)blockIdx.x << 8) + threadIdx.x) << 2;
    int n   = (int)(g >> 20);
    int rem = (int)(g & 1048575);
    int d   = rem >> 12;
    int hw  = rem & 4095;
    int tok = (n << 12) + hw;

    const float* erow = embed + d * NCODE;
    float q0 = erow[g_ind[tok + 0]];
    float q1 = erow[g_ind[tok + 1]];
    float q2 = erow[g_ind[tok + 2]];
    float q3 = erow[g_ind[tok + 3]];

    float4 xv = *(const float4*)(x + g);

    // scalar stores: outImg = d_out + 1 is only 4-byte aligned
    outImg[g + 0] = q0;
    outImg[g + 1] = q1;
    outImg[g + 2] = q2;
    outImg[g + 3] = q3;

    float d0 = q0 - xv.x, d1 = q1 - xv.y, d2 = q2 - xv.z, d3 = q3 - xv.w;
    float local = d0 * d0 + d1 * d1 + d2 * d2 + d3 * d3;

    #pragma unroll
    for (int off = 16; off > 0; off >>= 1)
        local += __shfl_down_sync(0xffffffffu, local, off);
    __shared__ float warpsum[8];
    int wid = threadIdx.x >> 5, lid = threadIdx.x & 31;
    if (lid == 0) warpsum[wid] = local;
    __syncthreads();
    if (threadIdx.x == 0) {
        float s = 0.f;
        #pragma unroll
        for (int w = 0; w < 8; ++w) s += warpsum[w];
        atomicAdd(&g_loss, (double)s);
        __threadfence();
        unsigned t = atomicInc(&g_done, 0xffffffffu);
        if (t == NGATHER - 1 && outLoss) {
            double total = atomicAdd(&g_loss, 0.0);   // ordered read
            outLoss[0] = (float)(0.25 * total / (double)IMG_ELEMS);
        }
    }
}

// ---------------------------------------------------------------------------
extern "C" void kernel_launch(void* const* d_in, const int* in_sizes, int n_in,
                              void* d_out, int out_size) {
    const float* x     = (const float*)d_in[0];   // [16,256,64,64] fp32
    const float* embed = (const float*)d_in[1];   // [256,1024] fp32
    float* out = (float*)d_out;

    int off = out_size - IMG_ELEMS;               // expected 1 (loss scalar first)
    float* outImg  = out + (off > 0 ? off : 0);
    float* outLoss = (off > 0) ? out : nullptr;

    cudaFuncSetAttribute(vq_mma_kernel,
                         cudaFuncAttributeMaxDynamicSharedMemorySize, S_TOTAL);

    e2_kernel<<<NCODE / 256, 256>>>(embed);
    prep_e_kernel<<<dim3(NCODE / 32, DIM / 32, 1), dim3(32, 8)>>>(embed);
    vq_mma_kernel<<<NTOK / 128, 512, S_TOTAL>>>(x);
    rescore_kernel<<<NTOK / 32, 256>>>(x);
    gather_kernel<<<NGATHER, 256>>>(x, embed, outImg, outLoss);
}